// round 11
// baseline (speedup 1.0000x reference)
#include <cuda_runtime.h>
#include <cuda_bf16.h>
#include <stdint.h>

#define S 32
#define T 512
#define F 512
#define STEPS 12
#define NEG 32
#define C 33
#define NTH 256

// smem layout in 4-byte words (total 56064 B -> 4 blocks/SM)
#define T_OFF    0                      // 32 classes x 256 u32 (bf16x2), XOR-swizzled
#define PP_OFF   8192                   // P: 256 k-pair rows x 12 f32 (6 steps/pass)
#define PART_OFF 11264                  // 8 kg x 192 (6 steps x 32 classes)
#define POS_OFF  12800                  // 768 positive partials (12 steps x 64 granules)
#define LG_OFF   13568                  // 396 logits (+4)
#define RS_OFF   13968                  // 32 row indices (classes 1..32)
#define RL_OFF   14000                  // 12 row losses (+4)
#define SMEM_WORDS 14016                // 56064 B

__device__ __nv_bfloat16 g_predT[(size_t)S * STEPS * T * F]; // (s,i,t,f)
__device__ __nv_bfloat16 g_latB[(size_t)S * T * F];
__device__ float g_part[S * T];

#define FMA2(a, b, t) asm("fma.rn.f32x2 %0, %1, %2, %0;" : "+l"(a) : "l"(b), "l"(t))

__device__ __forceinline__ uint32_t bf_lo(uint32_t v) { return __byte_perm(v, 0, 0x1044); }
__device__ __forceinline__ uint32_t bf_hi(uint32_t v) { return __byte_perm(v, 0, 0x3244); }

__global__ void init_kernel() {
    if (blockIdx.x == 0 && threadIdx.x == 0) g_part[0] = 0.f;
}

// ---------------------------------------------------------------------------
// Kernel 1: latent fp32 -> bf16
// ---------------------------------------------------------------------------
__global__ void latb_kernel(const float* __restrict__ lat) {
    const float4* in = (const float4*)lat;
    uint2* out = (uint2*)g_latB;
    int n4 = S * T * F / 4;
    for (int i = blockIdx.x * blockDim.x + threadIdx.x; i < n4;
         i += gridDim.x * blockDim.x) {
        float4 v = in[i];
        __nv_bfloat162 a = __floats2bfloat162_rn(v.x, v.y);
        __nv_bfloat162 b = __floats2bfloat162_rn(v.z, v.w);
        uint2 h;
        h.x = *(uint32_t*)&a;
        h.y = *(uint32_t*)&b;
        out[i] = h;
    }
}

// ---------------------------------------------------------------------------
// Kernel 2: transpose predictions (s,t,f,i) fp32 -> (s,i,t,f) bf16
// ---------------------------------------------------------------------------
__global__ void transpose_kernel(const float* __restrict__ pred) {
    __shared__ float sm[F * 13];
    int st = blockIdx.x;
    const float4* in = (const float4*)(pred + (size_t)st * (F * STEPS));
    for (int x = threadIdx.x; x < F * STEPS / 4; x += blockDim.x) {
        float4 v = in[x];
        int idx = 4 * x;
#pragma unroll
        for (int e = 0; e < 4; e++) {
            int f = (idx + e) / STEPS;
            int i = (idx + e) - f * STEPS;
            sm[f * 13 + i] = ((const float*)&v)[e];
        }
    }
    __syncthreads();
    int s = st >> 9;
    int t = st & (T - 1);
    for (int p = threadIdx.x; p < STEPS * 128; p += blockDim.x) {
        int i = p >> 7;
        int fp2 = p & 127;
        int f = fp2 * 4;
        __nv_bfloat162 h0 = __floats2bfloat162_rn(sm[f * 13 + i], sm[(f + 1) * 13 + i]);
        __nv_bfloat162 h1 = __floats2bfloat162_rn(sm[(f + 2) * 13 + i], sm[(f + 3) * 13 + i]);
        uint2 h;
        h.x = *(uint32_t*)&h0;
        h.y = *(uint32_t*)&h1;
        ((uint2*)(g_predT + ((size_t)((s * STEPS + i) * T + t)) * F))[fp2] = h;
    }
}

// ---------------------------------------------------------------------------
// Kernel 3: main. One block per (s,u). 4 blocks/SM.
// Two passes of 6 steps; positive class fused into staging.
// ---------------------------------------------------------------------------
__global__ void __launch_bounds__(NTH, 4)
main_kernel(const int* __restrict__ negi) {
    extern __shared__ uint32_t smw[];
    uint32_t* Tw     = smw + T_OFF;
    float*    Pp     = (float*)(smw + PP_OFF);
    float*    part   = (float*)(smw + PART_OFF);
    float*    posp   = (float*)(smw + POS_OFF);
    float*    logits = (float*)(smw + LG_OFF);
    int*      rowsm  = (int*)(smw + RS_OFF);
    float*    rowloss= (float*)(smw + RL_OFF);

    const int u = blockIdx.x;
    const int s = blockIdx.y;
    const int tid = threadIdx.x;
    const int kg   = tid >> 5;
    const int l    = tid & 31;
    const int cl   = l & 15;
    const int ksub = l >> 4;
    const int c0   = cl + 1;
    const int sw   = c0 & 7;
    const int gbase = kg * 8 + ksub * 4;
    const int rbase = kg * 32 + ksub * 16;
    const int o0 = ksub ? 4 : 0;
    const int o1 = ksub ? 8 : 4;
    const int o2 = ksub ? 0 : 8;

    // negative-class gather rows
    if (tid < 32) {
        int j = tid * T + u;
        int tsk = j >> 5;
        int raw = negi[s * (NEG * T) + j];
        rowsm[tid] = raw + (raw >= tsk ? 1 : 0);
    }
    __syncthreads();

    // --- stage 32 negative target rows (bf16, XOR-swizzled 16B granules) ---
    const uint4* latu4 = (const uint4*)g_latB;
    for (int x = tid; x < 32 * 64; x += NTH) {
        int cr = x >> 6;                 // array row = class cr+1
        int q  = x & 63;
        uint4 raw = latu4[((size_t)(s * T + rowsm[cr])) * 64 + q];
        *(uint4*)(Tw + cr * 256 + ((q ^ ((cr + 1) & 7)) << 2)) = raw;
    }

    const uint4* pu4 = (const uint4*)g_predT;

    for (int p = 0; p < 2; p++) {
        // --- stage P (6 steps) + fused positive partials ---
        for (int x = tid; x < 6 * 64; x += NTH) {
            int il = x % 6;
            int r = x / 6;
            int i = 6 * p + il;
            float2 v[4];
            unsigned long long pacc = 0ULL;
            if (i <= u) {
                uint4 raw = pu4[((size_t)((s * STEPS + i) * T + (u - i))) * 64 + r];
                const uint32_t* w = (const uint32_t*)&raw;
#pragma unroll
                for (int j = 0; j < 4; j++) {
                    v[j].x = __uint_as_float(bf_lo(w[j]));
                    v[j].y = __uint_as_float(bf_hi(w[j]));
                }
                uint4 t4 = latu4[((size_t)(s * T + u)) * 64 + r];
                const uint32_t* tw = (const uint32_t*)&t4;
#pragma unroll
                for (int j = 0; j < 4; j++) {
                    unsigned long long tv, pv;
                    asm("mov.b64 %0, {%1, %2};" : "=l"(tv) : "r"(bf_lo(tw[j])), "r"(bf_hi(tw[j])));
                    asm("mov.b64 %0, {%1, %2};" : "=l"(pv) : "f"(v[j].x), "f"(v[j].y));
                    FMA2(pacc, pv, tv);
                }
            } else {
                v[0] = v[1] = v[2] = v[3] = make_float2(0.f, 0.f);
            }
#pragma unroll
            for (int j = 0; j < 4; j++)
                *(float2*)(Pp + (4 * r + j) * 12 + 2 * il) = v[j];
            float2 pw = *(float2*)&pacc;
            posp[i * 64 + r] = pw.x + pw.y;
        }
        __syncthreads();

        // --- GEMM pass: 2 classes/lane, 16 k-pairs/lane, 6 steps ---
        unsigned long long aA[6], aB[6];
#pragma unroll
        for (int j = 0; j < 6; j++) { aA[j] = 0ULL; aB[j] = 0ULL; }

#pragma unroll
        for (int m = 0; m < 4; m++) {
            int tix = ((gbase + m) ^ sw) << 2;
            uint4 tq0 = *(const uint4*)(Tw + cl * 256 + tix);
            uint4 tq1 = *(const uint4*)(Tw + (cl + 16) * 256 + tix);
#pragma unroll
            for (int kk = 0; kk < 4; kk++) {
                int r = rbase + 4 * m + kk;
                const float* Pr = Pp + r * 12;
                uint32_t w0 = ((const uint32_t*)&tq0)[kk];
                uint32_t w1 = ((const uint32_t*)&tq1)[kk];
                unsigned long long tv0, tv1;
                asm("mov.b64 %0, {%1, %2};" : "=l"(tv0) : "r"(bf_lo(w0)), "r"(bf_hi(w0)));
                asm("mov.b64 %0, {%1, %2};" : "=l"(tv1) : "r"(bf_lo(w1)), "r"(bf_hi(w1)));
                ulonglong2 q0 = *(const ulonglong2*)(Pr + o0);
                ulonglong2 q1 = *(const ulonglong2*)(Pr + o1);
                ulonglong2 q2 = *(const ulonglong2*)(Pr + o2);
                FMA2(aA[0], q0.x, tv0); FMA2(aA[1], q0.y, tv0);
                FMA2(aB[0], q0.x, tv1); FMA2(aB[1], q0.y, tv1);
                FMA2(aA[2], q1.x, tv0); FMA2(aA[3], q1.y, tv0);
                FMA2(aB[2], q1.x, tv1); FMA2(aB[3], q1.y, tv1);
                FMA2(aA[4], q2.x, tv0); FMA2(aA[5], q2.y, tv0);
                FMA2(aB[4], q2.x, tv1); FMA2(aB[5], q2.y, tv1);
            }
        }

        float sA[6], sB[6];
#pragma unroll
        for (int j = 0; j < 6; j++) {
            float2 va = *(float2*)&aA[j];
            float2 vb = *(float2*)&aB[j];
            sA[j] = va.x + va.y;
            sB[j] = vb.x + vb.y;
        }
        // de-rotate + combine half-warps (rotation by 1 over 3 slots)
#pragma unroll
        for (int q = 0; q < 3; q++) {
#pragma unroll
            for (int e = 0; e < 2; e++) {
                const int qp = (q + 2) % 3;
                float vA = sA[2 * q + e] + __shfl_xor_sync(0xFFFFFFFFu, sA[2 * qp + e], 16);
                float vB = sB[2 * q + e] + __shfl_xor_sync(0xFFFFFFFFu, sB[2 * qp + e], 16);
                if (ksub == 0) {
                    int il = 2 * q + e;
                    part[kg * 192 + il * 32 + cl]      = vA;
                    part[kg * 192 + il * 32 + cl + 16] = vB;
                }
            }
        }
        __syncthreads();

        // --- reduce this pass's negatives into logits ---
        for (int o = tid; o < 6 * 32; o += NTH) {
            int il = o >> 5;
            int cc = o & 31;
            float ssum = 0.f;
#pragma unroll
            for (int g = 0; g < 8; g++) ssum += part[g * 192 + o];
            logits[(6 * p + il) * C + 1 + cc] = ssum;
        }
        __syncthreads();
    }

    // --- positive logits: warp-parallel posp reduction ---
    for (int i = kg; i < STEPS; i += 8) {
        float pv = posp[i * 64 + l] + posp[i * 64 + 32 + l];
#pragma unroll
        for (int off = 16; off > 0; off >>= 1)
            pv += __shfl_xor_sync(0xFFFFFFFFu, pv, off);
        if (l == 0) logits[i * C] = pv;
    }
    __syncthreads();

    // --- warp-parallel logsumexp: warp kg handles steps kg, kg+8 ---
    for (int i = kg; i < STEPS; i += 8) {
        float rl = 0.f;
        if (i <= u) {
            float v = logits[i * C + l];
            float v32 = logits[i * C + 32];
            float m = fmaxf(v, v32);
#pragma unroll
            for (int off = 16; off > 0; off >>= 1)
                m = fmaxf(m, __shfl_xor_sync(0xFFFFFFFFu, m, off));
            float e = __expf(v - m);
#pragma unroll
            for (int off = 16; off > 0; off >>= 1)
                e += __shfl_xor_sync(0xFFFFFFFFu, e, off);
            float total = e + __expf(v32 - m);
            rl = m + __logf(total) - logits[i * C];
        }
        if (l == 0) rowloss[i] = rl;
    }
    __syncthreads();
    if (tid == 0) {
        float bl = 0.f;
#pragma unroll
        for (int i = 0; i < STEPS; i++) bl += rowloss[i];
        g_part[s * T + u] = bl;
    }
}

// ---------------------------------------------------------------------------
// Kernel 4: deterministic final reduction
// ---------------------------------------------------------------------------
__global__ void reduce_kernel(float* __restrict__ out) {
    __shared__ float sm[512];
    int tid = threadIdx.x;
    float s0 = 0.f;
    for (int i = tid; i < S * T; i += 512) s0 += g_part[i];
    sm[tid] = s0;
    __syncthreads();
    for (int st = 256; st > 0; st >>= 1) {
        if (tid < st) sm[tid] += sm[tid + st];
        __syncthreads();
    }
    if (tid == 0) out[0] = sm[0];
}

extern "C" void kernel_launch(void* const* d_in, const int* in_sizes, int n_in,
                              void* d_out, int out_size) {
    const float* lat  = (const float*)d_in[0];
    const float* pred = (const float*)d_in[1];
    const int*   negi = (const int*)d_in[2];
    float* out = (float*)d_out;

    cudaFuncSetAttribute(main_kernel, cudaFuncAttributeMaxDynamicSharedMemorySize,
                         SMEM_WORDS * 4);

    init_kernel<<<1, 32>>>();
    latb_kernel<<<1024, 256>>>(lat);
    transpose_kernel<<<S * T, 256>>>(pred);
    main_kernel<<<dim3(T, S), NTH, SMEM_WORDS * 4>>>(negi);
    reduce_kernel<<<1, 512>>>(out);
}

// round 16
// speedup vs baseline: 1.0398x; 1.0398x over previous
#include <cuda_runtime.h>
#include <cuda_bf16.h>
#include <stdint.h>

#define S 32
#define T 512
#define F 512
#define STEPS 12
#define NEG 32
#define C 33
#define NTH 256

// dynamic smem layout (floats)
#define TF_OFF   0                      // T f32: 32 rows (classes 1..32) x 516
#define PP_OFF   16512                  // P f32: 256 kp-rows x 28
#define PART_OFF (PP_OFF + 7168)        // 4 kg x 384 (12 steps x 32 classes)
#define POS_OFF  (PART_OFF + 1536)      // 768 positive partials
#define LG_OFF   (POS_OFF + 768)        // 396 logits (+4)
#define RS_OFF   (LG_OFF + 400)         // 32 row indices
#define RL_OFF   (RS_OFF + 32)          // 12 row losses (+4)
#define SMEM_FLOATS (RL_OFF + 16)       // 26432 floats = 105728 B (x2/SM)

__device__ __nv_bfloat16 g_predT[(size_t)S * STEPS * T * F]; // (s,i,t,f)
__device__ __nv_bfloat16 g_latB[(size_t)S * T * F];
__device__ float g_part[S * T];

#define FMA2(a, b, t) asm("fma.rn.f32x2 %0, %1, %2, %0;" : "+l"(a) : "l"(b), "l"(t))

__device__ __forceinline__ uint32_t bf_lo(uint32_t v) { return __byte_perm(v, 0, 0x1044); }
__device__ __forceinline__ uint32_t bf_hi(uint32_t v) { return __byte_perm(v, 0, 0x3244); }

__global__ void init_kernel() {
    if (blockIdx.x == 0 && threadIdx.x == 0) g_part[0] = 0.f;
}

// ---------------------------------------------------------------------------
// Kernel 1: latent fp32 -> bf16
// ---------------------------------------------------------------------------
__global__ void latb_kernel(const float* __restrict__ lat) {
    const float4* in = (const float4*)lat;
    uint2* out = (uint2*)g_latB;
    int n4 = S * T * F / 4;
    for (int i = blockIdx.x * blockDim.x + threadIdx.x; i < n4;
         i += gridDim.x * blockDim.x) {
        float4 v = in[i];
        __nv_bfloat162 a = __floats2bfloat162_rn(v.x, v.y);
        __nv_bfloat162 b = __floats2bfloat162_rn(v.z, v.w);
        uint2 h;
        h.x = *(uint32_t*)&a;
        h.y = *(uint32_t*)&b;
        out[i] = h;
    }
}

// ---------------------------------------------------------------------------
// Kernel 2: transpose predictions (s,t,f,i) fp32 -> (s,i,t,f) bf16
// ---------------------------------------------------------------------------
__global__ void transpose_kernel(const float* __restrict__ pred) {
    __shared__ float sm[F * 13];
    int st = blockIdx.x;
    const float4* in = (const float4*)(pred + (size_t)st * (F * STEPS));
    for (int x = threadIdx.x; x < F * STEPS / 4; x += blockDim.x) {
        float4 v = in[x];
        int idx = 4 * x;
#pragma unroll
        for (int e = 0; e < 4; e++) {
            int f = (idx + e) / STEPS;
            int i = (idx + e) - f * STEPS;
            sm[f * 13 + i] = ((const float*)&v)[e];
        }
    }
    __syncthreads();
    int s = st >> 9;
    int t = st & (T - 1);
    for (int p = threadIdx.x; p < STEPS * 128; p += blockDim.x) {
        int i = p >> 7;
        int fp2 = p & 127;
        int f = fp2 * 4;
        __nv_bfloat162 h0 = __floats2bfloat162_rn(sm[f * 13 + i], sm[(f + 1) * 13 + i]);
        __nv_bfloat162 h1 = __floats2bfloat162_rn(sm[(f + 2) * 13 + i], sm[(f + 3) * 13 + i]);
        uint2 h;
        h.x = *(uint32_t*)&h0;
        h.y = *(uint32_t*)&h1;
        ((uint2*)(g_predT + ((size_t)((s * STEPS + i) * T + t)) * F))[fp2] = h;
    }
}

// ---------------------------------------------------------------------------
// Kernel 3: main. One block per (s,u). 2 blocks/SM, 128 regs/thread.
// Warp = (kg = k-quarter of 64 kp, sh = step-half of 6).
// Lane = (cl 0..7, ksub 0..3): classes {cl+1,cl+9,cl+17,cl+25}, 16 kp.
// T f32 in smem (stride 516, no in-loop conversion); P f32 stride 28 with
// ksub row-rotation -> all GEMM smem accesses at optimal wavefront count.
// ---------------------------------------------------------------------------
__global__ void __launch_bounds__(NTH, 2)
main_kernel(const int* __restrict__ negi) {
    extern __shared__ float smf[];
    float* Tf      = smf + TF_OFF;
    float* Pp      = smf + PP_OFF;
    float* part    = smf + PART_OFF;
    float* posp    = smf + POS_OFF;
    float* logits  = smf + LG_OFF;
    int*   rowsm   = (int*)(smf + RS_OFF);
    float* rowloss = smf + RL_OFF;

    const int u = blockIdx.x;
    const int s = blockIdx.y;
    const int tid = threadIdx.x;
    const int wid = tid >> 5;
    const int l   = tid & 31;
    const int kg  = wid & 3;     // k-quarter (64 kp)
    const int sh  = wid >> 2;    // step half (6 steps)
    const int cl  = l & 7;
    const int ksub = l >> 3;

    // negative-class gather rows (class c=tid+1)
    if (tid < 32) {
        int j = tid * T + u;
        int tsk = j >> 5;
        int raw = negi[s * (NEG * T) + j];
        rowsm[tid] = raw + (raw >= tsk ? 1 : 0);
    }
    __syncthreads();

    // --- stage T: bf16 gather -> f32 smem rows (stride 516) ---
    const uint4* latu4 = (const uint4*)g_latB;
    for (int x = tid; x < 32 * 64; x += NTH) {
        int c = x & 31;               // row (class c+1)
        int g = x >> 5;               // 32B granule (8 f32)
        uint4 raw = latu4[((size_t)(s * T + rowsm[c])) * 64 + g];
        float* dst = Tf + c * 516 + g * 8;
        float4 f0, f1;
        f0.x = __uint_as_float(bf_lo(raw.x)); f0.y = __uint_as_float(bf_hi(raw.x));
        f0.z = __uint_as_float(bf_lo(raw.y)); f0.w = __uint_as_float(bf_hi(raw.y));
        f1.x = __uint_as_float(bf_lo(raw.z)); f1.y = __uint_as_float(bf_hi(raw.z));
        f1.z = __uint_as_float(bf_lo(raw.w)); f1.w = __uint_as_float(bf_hi(raw.w));
        *(float4*)(dst)     = f0;
        *(float4*)(dst + 4) = f1;
    }

    // --- stage P (12 steps) + fused positive-class partials ---
    const uint4* pu4 = (const uint4*)g_predT;
    for (int x = tid; x < STEPS * 64; x += NTH) {
        int i = x % STEPS;
        int r = x / STEPS;            // 16B granule = 4 kp
        float2 v[4];
        unsigned long long pacc = 0ULL;
        if (i <= u) {
            uint4 raw = pu4[((size_t)((s * STEPS + i) * T + (u - i))) * 64 + r];
            const uint32_t* w = (const uint32_t*)&raw;
#pragma unroll
            for (int j = 0; j < 4; j++) {
                v[j].x = __uint_as_float(bf_lo(w[j]));
                v[j].y = __uint_as_float(bf_hi(w[j]));
            }
            uint4 t4 = latu4[((size_t)(s * T + u)) * 64 + r];
            const uint32_t* tw = (const uint32_t*)&t4;
#pragma unroll
            for (int j = 0; j < 4; j++) {
                unsigned long long tv, pv;
                asm("mov.b64 %0, {%1, %2};" : "=l"(tv) : "r"(bf_lo(tw[j])), "r"(bf_hi(tw[j])));
                asm("mov.b64 %0, {%1, %2};" : "=l"(pv) : "f"(v[j].x), "f"(v[j].y));
                FMA2(pacc, pv, tv);
            }
        } else {
            v[0] = v[1] = v[2] = v[3] = make_float2(0.f, 0.f);
        }
#pragma unroll
        for (int j = 0; j < 4; j++)
            *(float2*)(Pp + (4 * r + j) * 28 + 2 * i) = v[j];
        float2 pw = *(float2*)&pacc;
        posp[i * 64 + r] = pw.x + pw.y;
    }
    __syncthreads();

    // --- GEMM: 4 classes x 16 kp x 6 steps per lane ---
    unsigned long long acc[4][6];
#pragma unroll
    for (int c = 0; c < 4; c++)
#pragma unroll
        for (int il = 0; il < 6; il++) acc[c][il] = 0ULL;

    const float* Tb = Tf + cl * 516 + kg * 128 + ksub * 32;
    const float* Pb = Pp + (kg * 64 + ksub * 16) * 28 + sh * 12;

#pragma unroll
    for (int m = 0; m < 8; m++) {
        int w  = (m + ksub) & 7;       // rotated pair index (bank-spreads ksub)
        int fo = w * 4;                // float offset of kp-pair in T window
        ulonglong2 t0 = *(const ulonglong2*)(Tb + fo);
        ulonglong2 t1 = *(const ulonglong2*)(Tb + 8 * 516 + fo);
        ulonglong2 t2 = *(const ulonglong2*)(Tb + 16 * 516 + fo);
        ulonglong2 t3 = *(const ulonglong2*)(Tb + 24 * 516 + fo);
        const float* Pr0 = Pb + (w * 2) * 28;
        const float* Pr1 = Pr0 + 28;
#pragma unroll
        for (int q = 0; q < 3; q++) {
            ulonglong2 a = *(const ulonglong2*)(Pr0 + 4 * q);
            ulonglong2 b = *(const ulonglong2*)(Pr1 + 4 * q);
            FMA2(acc[0][2 * q], a.x, t0.x); FMA2(acc[0][2 * q + 1], a.y, t0.x);
            FMA2(acc[0][2 * q], b.x, t0.y); FMA2(acc[0][2 * q + 1], b.y, t0.y);
            FMA2(acc[1][2 * q], a.x, t1.x); FMA2(acc[1][2 * q + 1], a.y, t1.x);
            FMA2(acc[1][2 * q], b.x, t1.y); FMA2(acc[1][2 * q + 1], b.y, t1.y);
            FMA2(acc[2][2 * q], a.x, t2.x); FMA2(acc[2][2 * q + 1], a.y, t2.x);
            FMA2(acc[2][2 * q], b.x, t2.y); FMA2(acc[2][2 * q + 1], b.y, t2.y);
            FMA2(acc[3][2 * q], a.x, t3.x); FMA2(acc[3][2 * q + 1], a.y, t3.x);
            FMA2(acc[3][2 * q], b.x, t3.y); FMA2(acc[3][2 * q + 1], b.y, t3.y);
        }
    }

    // --- reduce over ksub (lanes cl, cl+8, cl+16, cl+24 hold same (c,i)) ---
#pragma unroll
    for (int c = 0; c < 4; c++) {
#pragma unroll
        for (int il = 0; il < 6; il++) {
            float2 v = *(float2*)&acc[c][il];
            float sv = v.x + v.y;
            sv += __shfl_xor_sync(0xFFFFFFFFu, sv, 8);
            sv += __shfl_xor_sync(0xFFFFFFFFu, sv, 16);
            if (ksub == 0)
                part[kg * 384 + (sh * 6 + il) * 32 + (cl + 8 * c)] = sv;
        }
    }
    __syncthreads();

    // --- assemble negative logits (reduce over 4 k-quarters) ---
    for (int o = tid; o < STEPS * 32; o += NTH) {
        int i = o >> 5;
        int cc = o & 31;
        float ssum = part[o] + part[384 + o] + part[768 + o] + part[1152 + o];
        logits[i * C + 1 + cc] = ssum;
    }
    // --- positive logits: warp-parallel posp reduction ---
    for (int i = wid; i < STEPS; i += 8) {
        float pv = posp[i * 64 + l] + posp[i * 64 + 32 + l];
#pragma unroll
        for (int off = 16; off > 0; off >>= 1)
            pv += __shfl_xor_sync(0xFFFFFFFFu, pv, off);
        if (l == 0) logits[i * C] = pv;
    }
    __syncthreads();

    // --- warp-parallel logsumexp ---
    for (int i = wid; i < STEPS; i += 8) {
        float rl = 0.f;
        if (i <= u) {
            float v = logits[i * C + l];
            float v32 = logits[i * C + 32];
            float m = fmaxf(v, v32);
#pragma unroll
            for (int off = 16; off > 0; off >>= 1)
                m = fmaxf(m, __shfl_xor_sync(0xFFFFFFFFu, m, off));
            float e = __expf(v - m);
#pragma unroll
            for (int off = 16; off > 0; off >>= 1)
                e += __shfl_xor_sync(0xFFFFFFFFu, e, off);
            float total = e + __expf(v32 - m);
            rl = m + __logf(total) - logits[i * C];
        }
        if (l == 0) rowloss[i] = rl;
    }
    __syncthreads();
    if (tid == 0) {
        float bl = 0.f;
#pragma unroll
        for (int i = 0; i < STEPS; i++) bl += rowloss[i];
        g_part[s * T + u] = bl;
    }
}

// ---------------------------------------------------------------------------
// Kernel 4: deterministic final reduction
// ---------------------------------------------------------------------------
__global__ void reduce_kernel(float* __restrict__ out) {
    __shared__ float sm[512];
    int tid = threadIdx.x;
    float s0 = 0.f;
    for (int i = tid; i < S * T; i += 512) s0 += g_part[i];
    sm[tid] = s0;
    __syncthreads();
    for (int st = 256; st > 0; st >>= 1) {
        if (tid < st) sm[tid] += sm[tid + st];
        __syncthreads();
    }
    if (tid == 0) out[0] = sm[0];
}

extern "C" void kernel_launch(void* const* d_in, const int* in_sizes, int n_in,
                              void* d_out, int out_size) {
    const float* lat  = (const float*)d_in[0];
    const float* pred = (const float*)d_in[1];
    const int*   negi = (const int*)d_in[2];
    float* out = (float*)d_out;

    cudaFuncSetAttribute(main_kernel, cudaFuncAttributeMaxDynamicSharedMemorySize,
                         SMEM_FLOATS * 4);

    init_kernel<<<1, 32>>>();
    latb_kernel<<<1024, 256>>>(lat);
    transpose_kernel<<<S * T, 256>>>(pred);
    main_kernel<<<dim3(T, S), NTH, SMEM_FLOATS * 4>>>(negi);
    reduce_kernel<<<1, 512>>>(out);
}